// round 8
// baseline (speedup 1.0000x reference)
#include <cuda_runtime.h>
#include <cstdint>

// Problem constants
#define N0 100000
#define N1 50000
#define N2 25000
#define N3 12500
#define E0 800000
#define E1 400000
#define E2 200000
#define D  256
#define MAXDEG 64
#define OVF_CAP 65536

// ---------------- scratch (device globals; no allocation allowed) ----------
__device__ float g_mean[N1 * D];
__device__ float g_h1[N1 * D];
__device__ float g_h2[N2 * D];
__device__ int   g_bcnt[N1];
__device__ int   g_bins[N1 * MAXDEG];
__device__ int2  g_ovf[OVF_CAP];
__device__ int   g_ovf_n;
__device__ int   g_is64;

// ---------------- zero counters + (optional) dtype detection -----------------
__global__ void zcnt_kernel(int* __restrict__ bcnt, int M,
                            const int* __restrict__ e, int do_detect) {
    int i = blockIdx.x * blockDim.x + threadIdx.x;
    if (i == 0) {
        g_ovf_n = 0;
        if (do_detect) {
            int is64 = 1;
            for (int k = 1; k < 64; k += 2)
                if (e[k] != 0) is64 = 0;
            g_is64 = is64;
        }
    }
    if (i < M) bcnt[i] = 0;
}

// ---------------- edge binning ------------------------------------------------
__global__ void bin_kernel(const void* __restrict__ eraw, int E,
                           int* __restrict__ bcnt, int* __restrict__ bins) {
    int i = blockIdx.x * blockDim.x + threadIdx.x;
    if (i >= E) return;
    int s, d;
    if (g_is64) {
        const long long* e = (const long long*)eraw;
        s = (int)e[i];
        d = (int)e[(long long)E + i];
    } else {
        const int* e = (const int*)eraw;
        s = e[i];
        d = e[E + i];
    }
    int slot = atomicAdd(&bcnt[d], 1);
    if (slot < MAXDEG) {
        bins[d * MAXDEG + slot] = s;
    } else {
        int o = atomicAdd(&g_ovf_n, 1);
        if (o < OVF_CAP) g_ovf[o] = make_int2(s, d);
    }
}

// ---------------- gather-mean: one warp per dst row (R4 exact) ----------------
__global__ void __launch_bounds__(256)
gather_kernel(const float* __restrict__ h,
              const int* __restrict__ bcnt,
              const int* __restrict__ bins,
              float* __restrict__ mean, int M) {
    int gw   = (blockIdx.x * blockDim.x + threadIdx.x) >> 5;
    int lane = threadIdx.x & 31;
    if (gw >= M) return;

    int deg = bcnt[gw];
    int nb  = min(deg, MAXDEG);

    int src0 = 0, src1 = 0;
    if (lane < nb)      src0 = bins[gw * MAXDEG + lane];
    if (lane + 32 < nb) src1 = bins[gw * MAXDEG + lane + 32];

    float4 acc0 = make_float4(0.f, 0.f, 0.f, 0.f);
    float4 acc1 = make_float4(0.f, 0.f, 0.f, 0.f);

    for (int i = 0; i < nb; i++) {
        int s = (i < 32) ? __shfl_sync(0xffffffffu, src0, i)
                         : __shfl_sync(0xffffffffu, src1, i - 32);
        const float4* row = (const float4*)(h + (size_t)s * D);
        float4 a = row[lane];
        float4 b = row[lane + 32];
        acc0.x += a.x; acc0.y += a.y; acc0.z += a.z; acc0.w += a.w;
        acc1.x += b.x; acc1.y += b.y; acc1.z += b.z; acc1.w += b.w;
    }

    float r = 1.0f / fmaxf((float)deg, 1.0f);
    float4* out = (float4*)(mean + (size_t)gw * D);
    acc0.x *= r; acc0.y *= r; acc0.z *= r; acc0.w *= r;
    acc1.x *= r; acc1.y *= r; acc1.z *= r; acc1.w *= r;
    out[lane]      = acc0;
    out[lane + 32] = acc1;
}

// ---------------- overflow fixup (expected no-op) ------------------------------
__device__ __forceinline__ void red_add_v4(float* p, float4 v) {
    asm volatile("red.global.add.v4.f32 [%0], {%1,%2,%3,%4};"
                 :: "l"(p), "f"(v.x), "f"(v.y), "f"(v.z), "f"(v.w)
                 : "memory");
}

__global__ void ovf_fix_kernel(const float* __restrict__ h,
                               const int* __restrict__ bcnt,
                               float* __restrict__ mean) {
    int n = g_ovf_n;
    if (n == 0) return;
    if (n > OVF_CAP) n = OVF_CAP;
    int lane = threadIdx.x & 31;
    int wid  = (blockIdx.x * blockDim.x + threadIdx.x) >> 5;
    int nw   = (gridDim.x * blockDim.x) >> 5;
    for (int k = wid; k < n; k += nw) {
        int2 sd = g_ovf[k];
        float r = 1.0f / fmaxf((float)bcnt[sd.y], 1.0f);
        const float4* row = (const float4*)(h + (size_t)sd.x * D);
        float* dst = mean + (size_t)sd.y * D;
#pragma unroll
        for (int j = 0; j < 2; j++) {
            int idx = lane + 32 * j;
            float4 v = row[idx];
            v.x *= r; v.y *= r; v.z *= r; v.w *= r;
            red_add_v4(dst + idx * 4, v);
        }
    }
}

// ---------------- fused SAGE GEMM (TF32, 160x128 block, 10 warps) -------------
// C[m,:] = mean[m] @ Wl + h_dst[m] @ Wr + b   (optional ReLU)
// Block 160x128, 10 warps (5x2), warp tile 32x64, BK=16, double-buffered.
// Identical As/Bs strides and fragment addressing to the validated R6 kernel;
// only change: +2 warps per CTA (more LDS-latency hiding), B staged by tid<256.

#define AS_STRIDE 20
#define BS_STRIDE 136
#define ABUF (160 * AS_STRIDE)
#define BBUF (16 * BS_STRIDE)

__device__ __forceinline__ unsigned f2tf(float f) {
    unsigned u;
    asm("cvt.rna.tf32.f32 %0, %1;" : "=r"(u) : "f"(f));
    return u;
}
__device__ __forceinline__ unsigned fu(float f) { return __float_as_uint(f); }

__device__ __forceinline__ void mma_tf32(float c[4], const unsigned a[4],
                                         unsigned b0, unsigned b1) {
    asm volatile(
        "mma.sync.aligned.m16n8k8.row.col.f32.tf32.tf32.f32 "
        "{%0,%1,%2,%3}, {%4,%5,%6,%7}, {%8,%9}, {%0,%1,%2,%3};"
        : "+f"(c[0]), "+f"(c[1]), "+f"(c[2]), "+f"(c[3])
        : "r"(a[0]), "r"(a[1]), "r"(a[2]), "r"(a[3]), "r"(b0), "r"(b1));
}

__global__ void __launch_bounds__(320, 2)
sage_gemm_tc(const float* __restrict__ A1,   // [M, 256] mean
             const float* __restrict__ A2,   // [M, 256] h_dst
             const float* __restrict__ Wl,
             const float* __restrict__ Wr,
             const float* __restrict__ bias,
             float* __restrict__ C,
             int M, int do_relu) {
    __shared__ float As[2 * ABUF];
    __shared__ float Bs[2 * BBUF];

    const int tid  = threadIdx.x;
    const int lane = tid & 31;
    const int warp = tid >> 5;      // 0..9
    const int wm   = warp >> 1;     // 0..4 -> m offset *32
    const int wn   = warp & 1;      // 0..1 -> n offset *64
    const int row0 = blockIdx.y * 160;
    const int col0 = blockIdx.x * 128;

    const int arow_l = tid >> 1;            // 0..159
    const int akslot = (tid & 1) * 8;
    const int brow_l = tid >> 4;            // valid for tid<256
    const int bcol_l = (tid & 15) * 8;

    const int garow = row0 + arow_l;

    float acc[2][8][4];
#pragma unroll
    for (int mi = 0; mi < 2; mi++)
#pragma unroll
        for (int ni = 0; ni < 8; ni++)
#pragma unroll
            for (int j = 0; j < 4; j++) acc[mi][ni][j] = 0.0f;

    const int lr = lane >> 2;
    const int lc = lane & 3;

    float va[8], wb[8];

    // it in [0,32): phase = it>>4, k0 = (it&15)*16
#define LOADG(it)                                                              \
    {                                                                          \
        const int phase_ = (it) >> 4;                                          \
        const int k0_    = ((it) & 15) << 4;                                   \
        const float* Ap = phase_ ? A2 : A1;                                    \
        const float* Bp = phase_ ? Wr : Wl;                                    \
        if (garow < M) {                                                       \
            const float4* ap = (const float4*)(Ap + (size_t)garow * D + k0_ + akslot); \
            *(float4*)&va[0] = ap[0];                                          \
            *(float4*)&va[4] = ap[1];                                          \
        } else {                                                               \
            _Pragma("unroll") for (int j = 0; j < 8; j++) va[j] = 0.0f;        \
        }                                                                      \
        if (tid < 256) {                                                       \
            const float4* bp = (const float4*)(Bp + (size_t)(k0_ + brow_l) * D + col0 + bcol_l); \
            *(float4*)&wb[0] = bp[0];                                          \
            *(float4*)&wb[4] = bp[1];                                          \
        }                                                                      \
    }

#define STORES(buf)                                                            \
    {                                                                          \
        float* as_ = &As[(buf) * ABUF + arow_l * AS_STRIDE + akslot];          \
        _Pragma("unroll") for (int j = 0; j < 8; j++)                          \
            as_[j] = __uint_as_float(f2tf(va[j]));                             \
        if (tid < 256) {                                                       \
            float* bs_ = &Bs[(buf) * BBUF + brow_l * BS_STRIDE + bcol_l];      \
            _Pragma("unroll") for (int j = 0; j < 8; j++)                      \
                bs_[j] = __uint_as_float(f2tf(wb[j]));                         \
        }                                                                      \
    }

#define COMPUTE(buf)                                                           \
    {                                                                          \
        const float* as_ = &As[(buf) * ABUF];                                  \
        const float* bs_ = &Bs[(buf) * BBUF];                                  \
        _Pragma("unroll") for (int ks = 0; ks < 2; ks++) {                     \
            const int k8 = ks * 8;                                             \
            unsigned a[2][4];                                                  \
            _Pragma("unroll") for (int mi = 0; mi < 2; mi++) {                 \
                const int rb = wm * 32 + mi * 16 + lr;                         \
                a[mi][0] = fu(as_[rb * AS_STRIDE + k8 + lc]);                  \
                a[mi][1] = fu(as_[(rb + 8) * AS_STRIDE + k8 + lc]);            \
                a[mi][2] = fu(as_[rb * AS_STRIDE + k8 + lc + 4]);              \
                a[mi][3] = fu(as_[(rb + 8) * AS_STRIDE + k8 + lc + 4]);        \
            }                                                                  \
            _Pragma("unroll") for (int ni = 0; ni < 8; ni++) {                 \
                const int nb = wn * 64 + ni * 8 + lr;                          \
                unsigned b0 = fu(bs_[(k8 + lc) * BS_STRIDE + nb]);             \
                unsigned b1 = fu(bs_[(k8 + lc + 4) * BS_STRIDE + nb]);         \
                mma_tf32(acc[0][ni], a[0], b0, b1);                            \
                mma_tf32(acc[1][ni], a[1], b0, b1);                            \
            }                                                                  \
        }                                                                      \
    }

    LOADG(0);
    STORES(0);
    __syncthreads();

    for (int it = 0; it < 32; it++) {
        if (it < 31) LOADG(it + 1);
        COMPUTE(it & 1);
        if (it < 31) STORES((it + 1) & 1);
        __syncthreads();
    }

    // epilogue
#pragma unroll
    for (int mi = 0; mi < 2; mi++) {
        const int r = row0 + wm * 32 + mi * 16 + lr;
#pragma unroll
        for (int ni = 0; ni < 8; ni++) {
            const int cidx = col0 + wn * 64 + ni * 8 + lc * 2;
            const float bb0 = bias[cidx];
            const float bb1 = bias[cidx + 1];
            float v0 = acc[mi][ni][0] + bb0;
            float v1 = acc[mi][ni][1] + bb1;
            float v2 = acc[mi][ni][2] + bb0;
            float v3 = acc[mi][ni][3] + bb1;
            if (do_relu) {
                v0 = fmaxf(v0, 0.f); v1 = fmaxf(v1, 0.f);
                v2 = fmaxf(v2, 0.f); v3 = fmaxf(v3, 0.f);
            }
            if (r < M) {
                C[(size_t)r * D + cidx]     = v0;
                C[(size_t)r * D + cidx + 1] = v1;
            }
            if (r + 8 < M) {
                C[(size_t)(r + 8) * D + cidx]     = v2;
                C[(size_t)(r + 8) * D + cidx + 1] = v3;
            }
        }
    }
}

// ---------------- launch -----------------------------------------------------
extern "C" void kernel_launch(void* const* d_in, const int* in_sizes, int n_in,
                              void* d_out, int out_size) {
    const float* x   = (const float*)d_in[0];
    const void*  e0  = d_in[1];
    const void*  e1  = d_in[2];
    const void*  e2  = d_in[3];
    const float* Wl0 = (const float*)d_in[4];
    const float* b0  = (const float*)d_in[5];
    const float* Wr0 = (const float*)d_in[6];
    const float* Wl1 = (const float*)d_in[7];
    const float* b1  = (const float*)d_in[8];
    const float* Wr1 = (const float*)d_in[9];
    const float* Wl2 = (const float*)d_in[10];
    const float* b2  = (const float*)d_in[11];
    const float* Wr2 = (const float*)d_in[12];
    float* out = (float*)d_out;

    float *mean, *h1, *h2;
    int *bcnt, *bins;
    cudaGetSymbolAddress((void**)&mean, g_mean);
    cudaGetSymbolAddress((void**)&h1,   g_h1);
    cudaGetSymbolAddress((void**)&h2,   g_h2);
    cudaGetSymbolAddress((void**)&bcnt, g_bcnt);
    cudaGetSymbolAddress((void**)&bins, g_bins);

    // ---- layer 0: x[N0] -> h1[N1]
    zcnt_kernel<<<(N1 + 255) / 256, 256>>>(bcnt, N1, (const int*)e0, 1);
    bin_kernel<<<(E0 + 255) / 256, 256>>>(e0, E0, bcnt, bins);
    gather_kernel<<<(N1 * 32 + 255) / 256, 256>>>(x, bcnt, bins, mean, N1);
    ovf_fix_kernel<<<2, 256>>>(x, bcnt, mean);
    sage_gemm_tc<<<dim3(2, (N1 + 159) / 160), 320>>>(
        mean, x, Wl0, Wr0, b0, h1, N1, 1);

    // ---- layer 1: h1[N1] -> h2[N2]
    zcnt_kernel<<<(N2 + 255) / 256, 256>>>(bcnt, N2, (const int*)e1, 0);
    bin_kernel<<<(E1 + 255) / 256, 256>>>(e1, E1, bcnt, bins);
    gather_kernel<<<(N2 * 32 + 255) / 256, 256>>>(h1, bcnt, bins, mean, N2);
    ovf_fix_kernel<<<2, 256>>>(h1, bcnt, mean);
    sage_gemm_tc<<<dim3(2, (N2 + 159) / 160), 320>>>(
        mean, h1, Wl1, Wr1, b1, h2, N2, 1);

    // ---- layer 2: h2[N2] -> out[N3] (no ReLU)
    zcnt_kernel<<<(N3 + 255) / 256, 256>>>(bcnt, N3, (const int*)e2, 0);
    bin_kernel<<<(E2 + 255) / 256, 256>>>(e2, E2, bcnt, bins);
    gather_kernel<<<(N3 * 32 + 255) / 256, 256>>>(h2, bcnt, bins, mean, N3);
    ovf_fix_kernel<<<2, 256>>>(h2, bcnt, mean);
    sage_gemm_tc<<<dim3(2, (N3 + 159) / 160), 320>>>(
        mean, h2, Wl2, Wr2, b2, out, N3, 0);
}

// round 9
// speedup vs baseline: 1.3385x; 1.3385x over previous
#include <cuda_runtime.h>
#include <cstdint>

// Problem constants
#define N0 100000
#define N1 50000
#define N2 25000
#define N3 12500
#define E0 800000
#define E1 400000
#define E2 200000
#define D  256
#define MAXDEG 64
#define OVF_CAP 65536

// ---------------- scratch (device globals; no allocation allowed) ----------
__device__ float g_mean[N1 * D];      // rounded means (A1)
__device__ float g_h1[N1 * D];        // rounded layer outputs
__device__ float g_h2[N2 * D];
__device__ float g_xt[N1 * D];        // tf32-rounded x[:N1] (A2 for layer 0)
__device__ float g_wt[6 * D * D];     // tf32-rounded weights
__device__ int   g_bcnt[N1];
__device__ int   g_bins[N1 * MAXDEG];
__device__ int2  g_ovf[OVF_CAP];
__device__ int   g_ovf_n;
__device__ int   g_is64;

__device__ __forceinline__ unsigned f2tf(float f) {
    unsigned u;
    asm("cvt.rna.tf32.f32 %0, %1;" : "=r"(u) : "f"(f));
    return u;
}
__device__ __forceinline__ unsigned fu(float f) { return __float_as_uint(f); }
__device__ __forceinline__ float u2f(unsigned u) { return __uint_as_float(u); }

// ---------------- pre-round weights (6 matrices) ------------------------------
__global__ void wcvt_kernel(const float* __restrict__ w0, const float* __restrict__ w1,
                            const float* __restrict__ w2, const float* __restrict__ w3,
                            const float* __restrict__ w4, const float* __restrict__ w5,
                            float4* __restrict__ dst) {
    int i = blockIdx.x * blockDim.x + threadIdx.x;   // 0 .. 6*16384-1
    if (i >= 6 * (D * D / 4)) return;
    int seg = i / (D * D / 4);
    int off = i - seg * (D * D / 4);
    const float4* src;
    switch (seg) {
        case 0: src = (const float4*)w0; break;
        case 1: src = (const float4*)w1; break;
        case 2: src = (const float4*)w2; break;
        case 3: src = (const float4*)w3; break;
        case 4: src = (const float4*)w4; break;
        default: src = (const float4*)w5; break;
    }
    float4 v = src[off];
    v.x = u2f(f2tf(v.x)); v.y = u2f(f2tf(v.y));
    v.z = u2f(f2tf(v.z)); v.w = u2f(f2tf(v.w));
    dst[i] = v;
}

// ---------------- pre-round x[:N1] --------------------------------------------
__global__ void xcvt_kernel(const float4* __restrict__ x, float4* __restrict__ xt) {
    int i = blockIdx.x * blockDim.x + threadIdx.x;
    if (i >= N1 * (D / 4)) return;
    float4 v = x[i];
    v.x = u2f(f2tf(v.x)); v.y = u2f(f2tf(v.y));
    v.z = u2f(f2tf(v.z)); v.w = u2f(f2tf(v.w));
    xt[i] = v;
}

// ---------------- zero counters + (optional) dtype detection -----------------
__global__ void zcnt_kernel(int* __restrict__ bcnt, int M,
                            const int* __restrict__ e, int do_detect) {
    int i = blockIdx.x * blockDim.x + threadIdx.x;
    if (i == 0) {
        g_ovf_n = 0;
        if (do_detect) {
            int is64 = 1;
            for (int k = 1; k < 64; k += 2)
                if (e[k] != 0) is64 = 0;
            g_is64 = is64;
        }
    }
    if (i < M) bcnt[i] = 0;
}

// ---------------- edge binning ------------------------------------------------
__global__ void bin_kernel(const void* __restrict__ eraw, int E,
                           int* __restrict__ bcnt, int* __restrict__ bins) {
    int i = blockIdx.x * blockDim.x + threadIdx.x;
    if (i >= E) return;
    int s, d;
    if (g_is64) {
        const long long* e = (const long long*)eraw;
        s = (int)e[i];
        d = (int)e[(long long)E + i];
    } else {
        const int* e = (const int*)eraw;
        s = e[i];
        d = e[E + i];
    }
    int slot = atomicAdd(&bcnt[d], 1);
    if (slot < MAXDEG) {
        bins[d * MAXDEG + slot] = s;
    } else {
        int o = atomicAdd(&g_ovf_n, 1);
        if (o < OVF_CAP) g_ovf[o] = make_int2(s, d);
    }
}

// ---------------- gather-mean: one warp per dst row (R4 body, rounded write) --
__global__ void __launch_bounds__(256)
gather_kernel(const float* __restrict__ h,
              const int* __restrict__ bcnt,
              const int* __restrict__ bins,
              float* __restrict__ mean, int M) {
    int gw   = (blockIdx.x * blockDim.x + threadIdx.x) >> 5;
    int lane = threadIdx.x & 31;
    if (gw >= M) return;

    int deg = bcnt[gw];
    int nb  = min(deg, MAXDEG);

    int src0 = 0, src1 = 0;
    if (lane < nb)      src0 = bins[gw * MAXDEG + lane];
    if (lane + 32 < nb) src1 = bins[gw * MAXDEG + lane + 32];

    float4 acc0 = make_float4(0.f, 0.f, 0.f, 0.f);
    float4 acc1 = make_float4(0.f, 0.f, 0.f, 0.f);

    for (int i = 0; i < nb; i++) {
        int s = (i < 32) ? __shfl_sync(0xffffffffu, src0, i)
                         : __shfl_sync(0xffffffffu, src1, i - 32);
        const float4* row = (const float4*)(h + (size_t)s * D);
        float4 a = row[lane];
        float4 b = row[lane + 32];
        acc0.x += a.x; acc0.y += a.y; acc0.z += a.z; acc0.w += a.w;
        acc1.x += b.x; acc1.y += b.y; acc1.z += b.z; acc1.w += b.w;
    }

    float r = 1.0f / fmaxf((float)deg, 1.0f);
    float4* out = (float4*)(mean + (size_t)gw * D);
    acc0.x = u2f(f2tf(acc0.x * r)); acc0.y = u2f(f2tf(acc0.y * r));
    acc0.z = u2f(f2tf(acc0.z * r)); acc0.w = u2f(f2tf(acc0.w * r));
    acc1.x = u2f(f2tf(acc1.x * r)); acc1.y = u2f(f2tf(acc1.y * r));
    acc1.z = u2f(f2tf(acc1.z * r)); acc1.w = u2f(f2tf(acc1.w * r));
    out[lane]      = acc0;
    out[lane + 32] = acc1;
}

// ---------------- overflow fixup (expected no-op) ------------------------------
__device__ __forceinline__ void red_add_v4(float* p, float4 v) {
    asm volatile("red.global.add.v4.f32 [%0], {%1,%2,%3,%4};"
                 :: "l"(p), "f"(v.x), "f"(v.y), "f"(v.z), "f"(v.w)
                 : "memory");
}

__global__ void ovf_fix_kernel(const float* __restrict__ h,
                               const int* __restrict__ bcnt,
                               float* __restrict__ mean) {
    int n = g_ovf_n;
    if (n == 0) return;
    if (n > OVF_CAP) n = OVF_CAP;
    int lane = threadIdx.x & 31;
    int wid  = (blockIdx.x * blockDim.x + threadIdx.x) >> 5;
    int nw   = (gridDim.x * blockDim.x) >> 5;
    for (int k = wid; k < n; k += nw) {
        int2 sd = g_ovf[k];
        float r = 1.0f / fmaxf((float)bcnt[sd.y], 1.0f);
        const float4* row = (const float4*)(h + (size_t)sd.x * D);
        float* dst = mean + (size_t)sd.y * D;
#pragma unroll
        for (int j = 0; j < 2; j++) {
            int idx = lane + 32 * j;
            float4 v = row[idx];
            v.x *= r; v.y *= r; v.z *= r; v.w *= r;
            red_add_v4(dst + idx * 4, v);
        }
    }
}

// ---------------- fused SAGE GEMM (TF32, R6 layout + cp.async staging) --------
// C[m,:] = mean[m] @ Wl + h_dst[m] @ Wr + b   (optional ReLU, optional tf32-round)
// Block 128x128, 8 warps (4x2), warp tile 32x64, BK=16, double-buffered.
// Inputs are pre-rounded to tf32, so staging is pure cp.async (no cvt, no STS).

#define AS_STRIDE 20
#define BS_STRIDE 136
#define ABUF (128 * AS_STRIDE)
#define BBUF (16 * BS_STRIDE)

__device__ __forceinline__ uint32_t smem_u32(const void* p) {
    uint32_t a;
    asm("{ .reg .u64 t; cvta.to.shared.u64 t, %1; cvt.u32.u64 %0, t; }"
        : "=r"(a) : "l"(p));
    return a;
}
__device__ __forceinline__ void cp_async16(uint32_t dst, const void* src, int srcsize) {
    asm volatile("cp.async.ca.shared.global [%0], [%1], 16, %2;"
                 :: "r"(dst), "l"(src), "r"(srcsize) : "memory");
}

__device__ __forceinline__ void mma_tf32(float c[4], const unsigned a[4],
                                         unsigned b0, unsigned b1) {
    asm volatile(
        "mma.sync.aligned.m16n8k8.row.col.f32.tf32.tf32.f32 "
        "{%0,%1,%2,%3}, {%4,%5,%6,%7}, {%8,%9}, {%0,%1,%2,%3};"
        : "+f"(c[0]), "+f"(c[1]), "+f"(c[2]), "+f"(c[3])
        : "r"(a[0]), "r"(a[1]), "r"(a[2]), "r"(a[3]), "r"(b0), "r"(b1));
}

__global__ void __launch_bounds__(256, 2)
sage_gemm_tc(const float* __restrict__ A1,   // [M, 256] rounded mean
             const float* __restrict__ A2,   // [M, 256] rounded h_dst
             const float* __restrict__ Wl,   // rounded
             const float* __restrict__ Wr,   // rounded
             const float* __restrict__ bias, // raw fp32
             float* __restrict__ C,
             int M, int do_relu, int round_out) {
    __shared__ float As[2 * ABUF];
    __shared__ float Bs[2 * BBUF];

    const int tid  = threadIdx.x;
    const int lane = tid & 31;
    const int warp = tid >> 5;
    const int wm   = warp >> 1;
    const int wn   = warp & 1;
    const int row0 = blockIdx.y * 128;
    const int col0 = blockIdx.x * 128;

    const int arow_l = tid >> 1;
    const int akslot = (tid & 1) * 8;
    const int brow_l = tid >> 4;
    const int bcol_l = (tid & 15) * 8;

    const int garow = row0 + arow_l;
    const int apred = (garow < M) ? 16 : 0;
    const size_t garow_c = (garow < M) ? (size_t)garow : 0;

    const uint32_t as_b = smem_u32(As) + (arow_l * AS_STRIDE + akslot) * 4;
    const uint32_t bs_b = smem_u32(Bs) + (brow_l * BS_STRIDE + bcol_l) * 4;

    float acc[2][8][4];
#pragma unroll
    for (int mi = 0; mi < 2; mi++)
#pragma unroll
        for (int ni = 0; ni < 8; ni++)
#pragma unroll
            for (int j = 0; j < 4; j++) acc[mi][ni][j] = 0.0f;

    const int lr = lane >> 2;
    const int lc = lane & 3;

    // it in [0,32): phase = it>>4, k0 = (it&15)*16
#define STAGE_ASYNC(it)                                                        \
    {                                                                          \
        const int phase_ = (it) >> 4;                                          \
        const int k0_    = ((it) & 15) << 4;                                   \
        const float* Ap = phase_ ? A2 : A1;                                    \
        const float* Bp = phase_ ? Wr : Wl;                                    \
        const int buf_ = (it) & 1;                                             \
        const float* ag = Ap + garow_c * D + k0_ + akslot;                     \
        cp_async16(as_b + buf_ * (ABUF * 4),      ag,     apred);              \
        cp_async16(as_b + buf_ * (ABUF * 4) + 16, ag + 4, apred);              \
        const float* bg = Bp + (size_t)(k0_ + brow_l) * D + col0 + bcol_l;     \
        cp_async16(bs_b + buf_ * (BBUF * 4),      bg,     16);                 \
        cp_async16(bs_b + buf_ * (BBUF * 4) + 16, bg + 4, 16);                 \
        asm volatile("cp.async.commit_group;" ::: "memory");                   \
    }

#define COMPUTE(buf)                                                           \
    {                                                                          \
        const float* as_ = &As[(buf) * ABUF];                                  \
        const float* bs_ = &Bs[(buf) * BBUF];                                  \
        _Pragma("unroll") for (int ks = 0; ks < 2; ks++) {                     \
            const int k8 = ks * 8;                                             \
            unsigned a[2][4];                                                  \
            _Pragma("unroll") for (int mi = 0; mi < 2; mi++) {                 \
                const int rb = wm * 32 + mi * 16 + lr;                         \
                a[mi][0] = fu(as_[rb * AS_STRIDE + k8 + lc]);                  \
                a[mi][1] = fu(as_[(rb + 8) * AS_STRIDE + k8 + lc]);            \
                a[mi][2] = fu(as_[rb * AS_STRIDE + k8 + lc + 4]);              \
                a[mi][3] = fu(as_[(rb + 8) * AS_STRIDE + k8 + lc + 4]);        \
            }                                                                  \
            _Pragma("unroll") for (int ni = 0; ni < 8; ni++) {                 \
                const int nb = wn * 64 + ni * 8 + lr;                          \
                unsigned b0 = fu(bs_[(k8 + lc) * BS_STRIDE + nb]);             \
                unsigned b1 = fu(bs_[(k8 + lc + 4) * BS_STRIDE + nb]);         \
                mma_tf32(acc[0][ni], a[0], b0, b1);                            \
                mma_tf32(acc[1][ni], a[1], b0, b1);                            \
            }                                                                  \
        }                                                                      \
    }

    STAGE_ASYNC(0);

    for (int it = 0; it < 32; it++) {
        asm volatile("cp.async.wait_group 0;" ::: "memory");
        __syncthreads();
        if (it < 31) STAGE_ASYNC(it + 1);
        COMPUTE(it & 1);
    }

    // epilogue
#pragma unroll
    for (int mi = 0; mi < 2; mi++) {
        const int r = row0 + wm * 32 + mi * 16 + lr;
#pragma unroll
        for (int ni = 0; ni < 8; ni++) {
            const int cidx = col0 + wn * 64 + ni * 8 + lc * 2;
            const float bb0 = bias[cidx];
            const float bb1 = bias[cidx + 1];
            float v0 = acc[mi][ni][0] + bb0;
            float v1 = acc[mi][ni][1] + bb1;
            float v2 = acc[mi][ni][2] + bb0;
            float v3 = acc[mi][ni][3] + bb1;
            if (do_relu) {
                v0 = fmaxf(v0, 0.f); v1 = fmaxf(v1, 0.f);
                v2 = fmaxf(v2, 0.f); v3 = fmaxf(v3, 0.f);
            }
            if (round_out) {
                v0 = u2f(f2tf(v0)); v1 = u2f(f2tf(v1));
                v2 = u2f(f2tf(v2)); v3 = u2f(f2tf(v3));
            }
            if (r < M) {
                C[(size_t)r * D + cidx]     = v0;
                C[(size_t)r * D + cidx + 1] = v1;
            }
            if (r + 8 < M) {
                C[(size_t)(r + 8) * D + cidx]     = v2;
                C[(size_t)(r + 8) * D + cidx + 1] = v3;
            }
        }
    }
}

// ---------------- launch -----------------------------------------------------
extern "C" void kernel_launch(void* const* d_in, const int* in_sizes, int n_in,
                              void* d_out, int out_size) {
    const float* x   = (const float*)d_in[0];
    const void*  e0  = d_in[1];
    const void*  e1  = d_in[2];
    const void*  e2  = d_in[3];
    const float* Wl0 = (const float*)d_in[4];
    const float* b0  = (const float*)d_in[5];
    const float* Wr0 = (const float*)d_in[6];
    const float* Wl1 = (const float*)d_in[7];
    const float* b1  = (const float*)d_in[8];
    const float* Wr1 = (const float*)d_in[9];
    const float* Wl2 = (const float*)d_in[10];
    const float* b2  = (const float*)d_in[11];
    const float* Wr2 = (const float*)d_in[12];
    float* out = (float*)d_out;

    float *mean, *h1, *h2, *xt, *wt;
    int *bcnt, *bins;
    cudaGetSymbolAddress((void**)&mean, g_mean);
    cudaGetSymbolAddress((void**)&h1,   g_h1);
    cudaGetSymbolAddress((void**)&h2,   g_h2);
    cudaGetSymbolAddress((void**)&xt,   g_xt);
    cudaGetSymbolAddress((void**)&wt,   g_wt);
    cudaGetSymbolAddress((void**)&bcnt, g_bcnt);
    cudaGetSymbolAddress((void**)&bins, g_bins);

    const float* wl0t = wt + 0 * D * D;
    const float* wr0t = wt + 1 * D * D;
    const float* wl1t = wt + 2 * D * D;
    const float* wr1t = wt + 3 * D * D;
    const float* wl2t = wt + 4 * D * D;
    const float* wr2t = wt + 5 * D * D;

    // pre-round weights + x dst-rows (independent of graph work)
    wcvt_kernel<<<(6 * D * D / 4 + 255) / 256, 256>>>(
        Wl0, Wr0, Wl1, Wr1, Wl2, Wr2, (float4*)wt);
    xcvt_kernel<<<(N1 * D / 4 + 255) / 256, 256>>>((const float4*)x, (float4*)xt);

    // ---- layer 0: x[N0] -> h1[N1]
    zcnt_kernel<<<(N1 + 255) / 256, 256>>>(bcnt, N1, (const int*)e0, 1);
    bin_kernel<<<(E0 + 255) / 256, 256>>>(e0, E0, bcnt, bins);
    gather_kernel<<<(N1 * 32 + 255) / 256, 256>>>(x, bcnt, bins, mean, N1);
    ovf_fix_kernel<<<2, 256>>>(x, bcnt, mean);
    sage_gemm_tc<<<dim3(2, (N1 + 127) / 128), 256>>>(
        mean, xt, wl0t, wr0t, b0, h1, N1, 1, 1);

    // ---- layer 1: h1[N1] -> h2[N2]
    zcnt_kernel<<<(N2 + 255) / 256, 256>>>(bcnt, N2, (const int*)e1, 0);
    bin_kernel<<<(E1 + 255) / 256, 256>>>(e1, E1, bcnt, bins);
    gather_kernel<<<(N2 * 32 + 255) / 256, 256>>>(h1, bcnt, bins, mean, N2);
    ovf_fix_kernel<<<2, 256>>>(h1, bcnt, mean);
    sage_gemm_tc<<<dim3(2, (N2 + 127) / 128), 256>>>(
        mean, h1, wl1t, wr1t, b1, h2, N2, 1, 1);

    // ---- layer 2: h2[N2] -> out[N3] (no ReLU, exact store)
    zcnt_kernel<<<(N3 + 255) / 256, 256>>>(bcnt, N3, (const int*)e2, 0);
    bin_kernel<<<(E2 + 255) / 256, 256>>>(e2, E2, bcnt, bins);
    gather_kernel<<<(N3 * 32 + 255) / 256, 256>>>(h2, bcnt, bins, mean, N3);
    ovf_fix_kernel<<<2, 256>>>(h2, bcnt, mean);
    sage_gemm_tc<<<dim3(2, (N3 + 127) / 128), 256>>>(
        mean, h2, wl2t, wr2t, b2, out, N3, 0, 0);
}

// round 10
// speedup vs baseline: 1.4097x; 1.0532x over previous
#include <cuda_runtime.h>
#include <cstdint>

// Problem constants
#define N0 100000
#define N1 50000
#define N2 25000
#define N3 12500
#define E0 800000
#define E1 400000
#define E2 200000
#define D  256
#define MAXDEG 64

// ---------------- scratch (device globals; no allocation allowed) ----------
__device__ float g_mean[N1 * D];         // rounded means (A1)
__device__ float g_h1[N1 * D];           // rounded layer outputs
__device__ float g_h2[N2 * D];
__device__ float g_wt[6 * D * D];        // tf32-rounded weights
__device__ int   g_bcnt[N1 + N2 + N3];   // per-layer degree arrays, zeroed once
__device__ int   g_bins[N1 * MAXDEG];    // per-dst src lists (reused per layer)
__device__ int   g_is64;

__device__ __forceinline__ unsigned f2tf(float f) {
    unsigned u;
    asm("cvt.rna.tf32.f32 %0, %1;" : "=r"(u) : "f"(f));
    return u;
}
__device__ __forceinline__ unsigned fu(float f) { return __float_as_uint(f); }
__device__ __forceinline__ float u2f(unsigned u) { return __uint_as_float(u); }

// ---------------- zero all counters + dtype detect (once) ---------------------
__global__ void zero_all_kernel(int* __restrict__ bcnt, const int* __restrict__ e) {
    int i = blockIdx.x * blockDim.x + threadIdx.x;
    if (i == 0) {
        int is64 = 1;
        for (int k = 1; k < 64; k += 2)
            if (e[k] != 0) is64 = 0;
        g_is64 = is64;
    }
    if (i < N1 + N2 + N3) bcnt[i] = 0;
}

// ---------------- pre-round weights (6 matrices) ------------------------------
__global__ void wcvt_kernel(const float* __restrict__ w0, const float* __restrict__ w1,
                            const float* __restrict__ w2, const float* __restrict__ w3,
                            const float* __restrict__ w4, const float* __restrict__ w5,
                            float4* __restrict__ dst) {
    int i = blockIdx.x * blockDim.x + threadIdx.x;   // 0 .. 6*16384-1
    if (i >= 6 * (D * D / 4)) return;
    int seg = i / (D * D / 4);
    int off = i - seg * (D * D / 4);
    const float4* src;
    switch (seg) {
        case 0: src = (const float4*)w0; break;
        case 1: src = (const float4*)w1; break;
        case 2: src = (const float4*)w2; break;
        case 3: src = (const float4*)w3; break;
        case 4: src = (const float4*)w4; break;
        default: src = (const float4*)w5; break;
    }
    float4 v = src[off];
    v.x = u2f(f2tf(v.x)); v.y = u2f(f2tf(v.y));
    v.z = u2f(f2tf(v.z)); v.w = u2f(f2tf(v.w));
    dst[i] = v;
}

// ---------------- edge binning ------------------------------------------------
__global__ void bin_kernel(const void* __restrict__ eraw, int E,
                           int* __restrict__ bcnt, int* __restrict__ bins) {
    int i = blockIdx.x * blockDim.x + threadIdx.x;
    if (i >= E) return;
    int s, d;
    if (g_is64) {
        const long long* e = (const long long*)eraw;
        s = (int)e[i];
        d = (int)e[(long long)E + i];
    } else {
        const int* e = (const int*)eraw;
        s = e[i];
        d = e[E + i];
    }
    int slot = atomicAdd(&bcnt[d], 1);
    if (slot < MAXDEG) bins[d * MAXDEG + slot] = s;
    // slot >= MAXDEG: gather rescans the edge list for this dst (never in practice)
}

// ---------------- gather-mean: one warp per dst row ---------------------------
__global__ void __launch_bounds__(256)
gather_kernel(const float* __restrict__ h,
              const int* __restrict__ bcnt,
              const int* __restrict__ bins,
              const void* __restrict__ eraw, int E,
              float* __restrict__ mean, int M) {
    int gw   = (blockIdx.x * blockDim.x + threadIdx.x) >> 5;
    int lane = threadIdx.x & 31;
    if (gw >= M) return;

    int deg = bcnt[gw];

    float4 acc0 = make_float4(0.f, 0.f, 0.f, 0.f);
    float4 acc1 = make_float4(0.f, 0.f, 0.f, 0.f);

    if (deg <= MAXDEG) {
        // fast path (always taken in practice)
        int src0 = 0, src1 = 0;
        if (lane < deg)      src0 = bins[gw * MAXDEG + lane];
        if (lane + 32 < deg) src1 = bins[gw * MAXDEG + lane + 32];
        for (int i = 0; i < deg; i++) {
            int s = (i < 32) ? __shfl_sync(0xffffffffu, src0, i)
                             : __shfl_sync(0xffffffffu, src1, i - 32);
            const float4* row = (const float4*)(h + (size_t)s * D);
            float4 a = row[lane];
            float4 b = row[lane + 32];
            acc0.x += a.x; acc0.y += a.y; acc0.z += a.z; acc0.w += a.w;
            acc1.x += b.x; acc1.y += b.y; acc1.z += b.z; acc1.w += b.w;
        }
    } else {
        // overflow: full rescan of the edge list (correct, never expected)
        int is64 = g_is64;
        for (int i = 0; i < E; i++) {
            int s, d;
            if (is64) {
                const long long* e = (const long long*)eraw;
                d = (int)e[(long long)E + i];
                if (d != gw) continue;
                s = (int)e[i];
            } else {
                const int* e = (const int*)eraw;
                d = e[E + i];
                if (d != gw) continue;
                s = e[i];
            }
            const float4* row = (const float4*)(h + (size_t)s * D);
            float4 a = row[lane];
            float4 b = row[lane + 32];
            acc0.x += a.x; acc0.y += a.y; acc0.z += a.z; acc0.w += a.w;
            acc1.x += b.x; acc1.y += b.y; acc1.z += b.z; acc1.w += b.w;
        }
    }

    float r = 1.0f / fmaxf((float)deg, 1.0f);
    float4* out = (float4*)(mean + (size_t)gw * D);
    acc0.x = u2f(f2tf(acc0.x * r)); acc0.y = u2f(f2tf(acc0.y * r));
    acc0.z = u2f(f2tf(acc0.z * r)); acc0.w = u2f(f2tf(acc0.w * r));
    acc1.x = u2f(f2tf(acc1.x * r)); acc1.y = u2f(f2tf(acc1.y * r));
    acc1.z = u2f(f2tf(acc1.z * r)); acc1.w = u2f(f2tf(acc1.w * r));
    out[lane]      = acc0;
    out[lane + 32] = acc1;
}

// ---------------- fused SAGE GEMM (TF32, R6 layout + cp.async staging) --------
// C[m,:] = mean[m] @ Wl + h_dst[m] @ Wr + b   (optional ReLU, optional tf32-round)
// Block 128x128, 8 warps (4x2), warp tile 32x64, BK=16, double-buffered.
// A1/Wl/Wr pre-rounded to tf32. A2 may be raw fp32 (mma truncates low bits).

#define AS_STRIDE 20
#define BS_STRIDE 136
#define ABUF (128 * AS_STRIDE)
#define BBUF (16 * BS_STRIDE)

__device__ __forceinline__ uint32_t smem_u32(const void* p) {
    uint32_t a;
    asm("{ .reg .u64 t; cvta.to.shared.u64 t, %1; cvt.u32.u64 %0, t; }"
        : "=r"(a) : "l"(p));
    return a;
}
__device__ __forceinline__ void cp_async16(uint32_t dst, const void* src, int srcsize) {
    asm volatile("cp.async.ca.shared.global [%0], [%1], 16, %2;"
                 :: "r"(dst), "l"(src), "r"(srcsize) : "memory");
}

__device__ __forceinline__ void mma_tf32(float c[4], const unsigned a[4],
                                         unsigned b0, unsigned b1) {
    asm volatile(
        "mma.sync.aligned.m16n8k8.row.col.f32.tf32.tf32.f32 "
        "{%0,%1,%2,%3}, {%4,%5,%6,%7}, {%8,%9}, {%0,%1,%2,%3};"
        : "+f"(c[0]), "+f"(c[1]), "+f"(c[2]), "+f"(c[3])
        : "r"(a[0]), "r"(a[1]), "r"(a[2]), "r"(a[3]), "r"(b0), "r"(b1));
}

__global__ void __launch_bounds__(256, 2)
sage_gemm_tc(const float* __restrict__ A1,   // [M, 256] rounded mean
             const float* __restrict__ A2,   // [M, 256] h_dst (rounded or raw)
             const float* __restrict__ Wl,   // rounded
             const float* __restrict__ Wr,   // rounded
             const float* __restrict__ bias, // raw fp32
             float* __restrict__ C,
             int M, int do_relu, int round_out) {
    __shared__ float As[2 * ABUF];
    __shared__ float Bs[2 * BBUF];

    const int tid  = threadIdx.x;
    const int lane = tid & 31;
    const int warp = tid >> 5;
    const int wm   = warp >> 1;
    const int wn   = warp & 1;
    const int row0 = blockIdx.y * 128;
    const int col0 = blockIdx.x * 128;

    const int arow_l = tid >> 1;
    const int akslot = (tid & 1) * 8;
    const int brow_l = tid >> 4;
    const int bcol_l = (tid & 15) * 8;

    const int garow = row0 + arow_l;
    const int apred = (garow < M) ? 16 : 0;
    const size_t garow_c = (garow < M) ? (size_t)garow : 0;

    const uint32_t as_b = smem_u32(As) + (arow_l * AS_STRIDE + akslot) * 4;
    const uint32_t bs_b = smem_u32(Bs) + (brow_l * BS_STRIDE + bcol_l) * 4;

    float acc[2][8][4];
#pragma unroll
    for (int mi = 0; mi < 2; mi++)
#pragma unroll
        for (int ni = 0; ni < 8; ni++)
#pragma unroll
            for (int j = 0; j < 4; j++) acc[mi][ni][j] = 0.0f;

    const int lr = lane >> 2;
    const int lc = lane & 3;

    // it in [0,32): phase = it>>4, k0 = (it&15)*16
#define STAGE_ASYNC(it)                                                        \
    {                                                                          \
        const int phase_ = (it) >> 4;                                          \
        const int k0_    = ((it) & 15) << 4;                                   \
        const float* Ap = phase_ ? A2 : A1;                                    \
        const float* Bp = phase_ ? Wr : Wl;                                    \
        const int buf_ = (it) & 1;                                             \
        const float* ag = Ap + garow_c * D + k0_ + akslot;                     \
        cp_async16(as_b + buf_ * (ABUF * 4),      ag,     apred);              \
        cp_async16(as_b + buf_ * (ABUF * 4) + 16, ag + 4, apred);              \
        const float* bg = Bp + (size_t)(k0_ + brow_l) * D + col0 + bcol_l;     \
        cp_async16(bs_b + buf_ * (BBUF * 4),      bg,     16);                 \
        cp_async16(bs_b + buf_ * (BBUF * 4) + 16, bg + 4, 16);                 \
        asm volatile("cp.async.commit_group;" ::: "memory");                   \
    }

#define COMPUTE(buf)                                                           \
    {                                                                          \
        const float* as_ = &As[(buf) * ABUF];                                  \
        const float* bs_ = &Bs[(buf) * BBUF];                                  \
        _Pragma("unroll") for (int ks = 0; ks < 2; ks++) {                     \
            const int k8 = ks * 8;                                             \
            unsigned a[2][4];                                                  \
            _Pragma("unroll") for (int mi = 0; mi < 2; mi++) {                 \
                const int rb = wm * 32 + mi * 16 + lr;                         \
                a[mi][0] = fu(as_[rb * AS_STRIDE + k8 + lc]);                  \
                a[mi][1] = fu(as_[(rb + 8) * AS_STRIDE + k8 + lc]);            \
                a[mi][2] = fu(as_[rb * AS_STRIDE + k8 + lc + 4]);              \
                a[mi][3] = fu(as_[(rb + 8) * AS_STRIDE + k8 + lc + 4]);        \
            }                                                                  \
            _Pragma("unroll") for (int ni = 0; ni < 8; ni++) {                 \
                const int nb = wn * 64 + ni * 8 + lr;                          \
                unsigned b0 = fu(bs_[(k8 + lc) * BS_STRIDE + nb]);             \
                unsigned b1 = fu(bs_[(k8 + lc + 4) * BS_STRIDE + nb]);         \
                mma_tf32(acc[0][ni], a[0], b0, b1);                            \
                mma_tf32(acc[1][ni], a[1], b0, b1);                            \
            }                                                                  \
        }                                                                      \
    }

    STAGE_ASYNC(0);

    for (int it = 0; it < 32; it++) {
        asm volatile("cp.async.wait_group 0;" ::: "memory");
        __syncthreads();
        if (it < 31) STAGE_ASYNC(it + 1);
        COMPUTE(it & 1);
    }

    // epilogue
#pragma unroll
    for (int mi = 0; mi < 2; mi++) {
        const int r = row0 + wm * 32 + mi * 16 + lr;
#pragma unroll
        for (int ni = 0; ni < 8; ni++) {
            const int cidx = col0 + wn * 64 + ni * 8 + lc * 2;
            const float bb0 = bias[cidx];
            const float bb1 = bias[cidx + 1];
            float v0 = acc[mi][ni][0] + bb0;
            float v1 = acc[mi][ni][1] + bb1;
            float v2 = acc[mi][ni][2] + bb0;
            float v3 = acc[mi][ni][3] + bb1;
            if (do_relu) {
                v0 = fmaxf(v0, 0.f); v1 = fmaxf(v1, 0.f);
                v2 = fmaxf(v2, 0.f); v3 = fmaxf(v3, 0.f);
            }
            if (round_out) {
                v0 = u2f(f2tf(v0)); v1 = u2f(f2tf(v1));
                v2 = u2f(f2tf(v2)); v3 = u2f(f2tf(v3));
            }
            if (r < M) {
                C[(size_t)r * D + cidx]     = v0;
                C[(size_t)r * D + cidx + 1] = v1;
            }
            if (r + 8 < M) {
                C[(size_t)(r + 8) * D + cidx]     = v2;
                C[(size_t)(r + 8) * D + cidx + 1] = v3;
            }
        }
    }
}

// ---------------- launch -----------------------------------------------------
extern "C" void kernel_launch(void* const* d_in, const int* in_sizes, int n_in,
                              void* d_out, int out_size) {
    const float* x   = (const float*)d_in[0];
    const void*  e0  = d_in[1];
    const void*  e1  = d_in[2];
    const void*  e2  = d_in[3];
    const float* Wl0 = (const float*)d_in[4];
    const float* b0  = (const float*)d_in[5];
    const float* Wr0 = (const float*)d_in[6];
    const float* Wl1 = (const float*)d_in[7];
    const float* b1  = (const float*)d_in[8];
    const float* Wr1 = (const float*)d_in[9];
    const float* Wl2 = (const float*)d_in[10];
    const float* b2  = (const float*)d_in[11];
    const float* Wr2 = (const float*)d_in[12];
    float* out = (float*)d_out;

    float *mean, *h1, *h2, *wt;
    int *bcnt, *bins;
    cudaGetSymbolAddress((void**)&mean, g_mean);
    cudaGetSymbolAddress((void**)&h1,   g_h1);
    cudaGetSymbolAddress((void**)&h2,   g_h2);
    cudaGetSymbolAddress((void**)&wt,   g_wt);
    cudaGetSymbolAddress((void**)&bcnt, g_bcnt);
    cudaGetSymbolAddress((void**)&bins, g_bins);

    int* bcnt0 = bcnt;
    int* bcnt1 = bcnt + N1;
    int* bcnt2 = bcnt + N1 + N2;

    const float* wl0t = wt + 0 * D * D;
    const float* wr0t = wt + 1 * D * D;
    const float* wl1t = wt + 2 * D * D;
    const float* wr1t = wt + 3 * D * D;
    const float* wl2t = wt + 4 * D * D;
    const float* wr2t = wt + 5 * D * D;

    zero_all_kernel<<<(N1 + N2 + N3 + 255) / 256, 256>>>(bcnt, (const int*)e0);
    wcvt_kernel<<<(6 * D * D / 4 + 255) / 256, 256>>>(
        Wl0, Wr0, Wl1, Wr1, Wl2, Wr2, (float4*)wt);

    // ---- layer 0: x[N0] -> h1[N1]
    bin_kernel<<<(E0 + 255) / 256, 256>>>(e0, E0, bcnt0, bins);
    gather_kernel<<<(N1 * 32 + 255) / 256, 256>>>(x, bcnt0, bins, e0, E0, mean, N1);
    sage_gemm_tc<<<dim3(2, (N1 + 127) / 128), 256>>>(
        mean, x, wl0t, wr0t, b0, h1, N1, 1, 1);

    // ---- layer 1: h1[N1] -> h2[N2]
    bin_kernel<<<(E1 + 255) / 256, 256>>>(e1, E1, bcnt1, bins);
    gather_kernel<<<(N2 * 32 + 255) / 256, 256>>>(h1, bcnt1, bins, e1, E1, mean, N2);
    sage_gemm_tc<<<dim3(2, (N2 + 127) / 128), 256>>>(
        mean, h1, wl1t, wr1t, b1, h2, N2, 1, 1);

    // ---- layer 2: h2[N2] -> out[N3] (no ReLU, exact store)
    bin_kernel<<<(E2 + 255) / 256, 256>>>(e2, E2, bcnt2, bins);
    gather_kernel<<<(N3 * 32 + 255) / 256, 256>>>(h2, bcnt2, bins, e2, E2, mean, N3);
    sage_gemm_tc<<<dim3(2, (N3 + 127) / 128), 256>>>(
        mean, h2, wl2t, wr2t, b2, out, N3, 0, 0);
}

// round 12
// speedup vs baseline: 1.4345x; 1.0176x over previous
#include <cuda_runtime.h>
#include <cstdint>

// Problem constants
#define N0 100000
#define N1 50000
#define N2 25000
#define N3 12500
#define E0 800000
#define E1 400000
#define E2 200000
#define D  256
#define MAXDEG 64

// ---------------- scratch (device globals; no allocation allowed) ----------
__device__ float g_mean[N1 * D];          // rounded means (A1)
__device__ float g_h1[N1 * D];            // rounded layer outputs
__device__ float g_h2[N2 * D];
__device__ float g_wt[6 * D * D];         // tf32-rounded weights
__device__ int   g_bcnt[N1 + N2 + N3];    // per-layer degree arrays
__device__ int   g_bins0[N1 * MAXDEG];    // per-layer per-dst src lists
__device__ int   g_bins1[N2 * MAXDEG];
__device__ int   g_bins2[N3 * MAXDEG];
__device__ int   g_is64;

__device__ __forceinline__ unsigned f2tf(float f) {
    unsigned u;
    asm("cvt.rna.tf32.f32 %0, %1;" : "=r"(u) : "f"(f));
    return u;
}
__device__ __forceinline__ unsigned fu(float f) { return __float_as_uint(f); }
__device__ __forceinline__ float u2f(unsigned u) { return __uint_as_float(u); }

// ---------------- prep: zero counters + detect + round weights (one kernel) ---
#define NCNT (N1 + N2 + N3)
__global__ void prep_kernel(const int* __restrict__ e0,
                            const float* __restrict__ w0, const float* __restrict__ w1,
                            const float* __restrict__ w2, const float* __restrict__ w3,
                            const float* __restrict__ w4, const float* __restrict__ w5,
                            int* __restrict__ bcnt, float4* __restrict__ wt) {
    int i = blockIdx.x * blockDim.x + threadIdx.x;
    if (i == 0) {
        int is64 = 1;
        for (int k = 1; k < 64; k += 2)
            if (e0[k] != 0) is64 = 0;
        g_is64 = is64;
    }
    if (i < NCNT) bcnt[i] = 0;
    int j = i - NCNT;
    if (j >= 0 && j < 6 * (D * D / 4)) {
        int seg = j / (D * D / 4);
        int off = j - seg * (D * D / 4);
        const float4* src;
        switch (seg) {
            case 0: src = (const float4*)w0; break;
            case 1: src = (const float4*)w1; break;
            case 2: src = (const float4*)w2; break;
            case 3: src = (const float4*)w3; break;
            case 4: src = (const float4*)w4; break;
            default: src = (const float4*)w5; break;
        }
        float4 v = src[off];
        v.x = u2f(f2tf(v.x)); v.y = u2f(f2tf(v.y));
        v.z = u2f(f2tf(v.z)); v.w = u2f(f2tf(v.w));
        wt[j] = v;
    }
}
#define PREP_THREADS (NCNT + 6 * (D * D / 4))

// ---------------- merged edge binning (all 3 layers, one launch) ---------------
__global__ void bin_all_kernel(const void* __restrict__ e0raw,
                               const void* __restrict__ e1raw,
                               const void* __restrict__ e2raw,
                               int* __restrict__ bcnt) {
    int i = blockIdx.x * blockDim.x + threadIdx.x;
    const void* eraw;
    int E, li;
    int* bc;
    int* bins;
    if (i < E0) {
        eraw = e0raw; E = E0; li = i; bc = bcnt; bins = g_bins0;
    } else if (i < E0 + E1) {
        eraw = e1raw; E = E1; li = i - E0; bc = bcnt + N1; bins = g_bins1;
    } else if (i < E0 + E1 + E2) {
        eraw = e2raw; E = E2; li = i - E0 - E1; bc = bcnt + N1 + N2; bins = g_bins2;
    } else {
        return;
    }
    int s, d;
    if (g_is64) {
        const long long* e = (const long long*)eraw;
        s = (int)e[li];
        d = (int)e[(long long)E + li];
    } else {
        const int* e = (const int*)eraw;
        s = e[li];
        d = e[E + li];
    }
    int slot = atomicAdd(&bc[d], 1);
    if (slot < MAXDEG) bins[d * MAXDEG + slot] = s;
    // slot >= MAXDEG: gather rescans the edge list for this dst (never in practice)
}

// ---------------- gather-mean: one warp per dst row (R10 exact) ----------------
__global__ void __launch_bounds__(256)
gather_kernel(const float* __restrict__ h,
              const int* __restrict__ bcnt,
              const int* __restrict__ bins,
              const void* __restrict__ eraw, int E,
              float* __restrict__ mean, int M) {
    int gw   = (blockIdx.x * blockDim.x + threadIdx.x) >> 5;
    int lane = threadIdx.x & 31;
    if (gw >= M) return;

    int deg = bcnt[gw];

    float4 acc0 = make_float4(0.f, 0.f, 0.f, 0.f);
    float4 acc1 = make_float4(0.f, 0.f, 0.f, 0.f);

    if (deg <= MAXDEG) {
        int src0 = 0, src1 = 0;
        if (lane < deg)      src0 = bins[gw * MAXDEG + lane];
        if (lane + 32 < deg) src1 = bins[gw * MAXDEG + lane + 32];
        for (int i = 0; i < deg; i++) {
            int s = (i < 32) ? __shfl_sync(0xffffffffu, src0, i)
                             : __shfl_sync(0xffffffffu, src1, i - 32);
            const float4* row = (const float4*)(h + (size_t)s * D);
            float4 a = row[lane];
            float4 b = row[lane + 32];
            acc0.x += a.x; acc0.y += a.y; acc0.z += a.z; acc0.w += a.w;
            acc1.x += b.x; acc1.y += b.y; acc1.z += b.z; acc1.w += b.w;
        }
    } else {
        int is64 = g_is64;
        for (int i = 0; i < E; i++) {
            int s, d;
            if (is64) {
                const long long* e = (const long long*)eraw;
                d = (int)e[(long long)E + i];
                if (d != gw) continue;
                s = (int)e[i];
            } else {
                const int* e = (const int*)eraw;
                d = e[E + i];
                if (d != gw) continue;
                s = e[i];
            }
            const float4* row = (const float4*)(h + (size_t)s * D);
            float4 a = row[lane];
            float4 b = row[lane + 32];
            acc0.x += a.x; acc0.y += a.y; acc0.z += a.z; acc0.w += a.w;
            acc1.x += b.x; acc1.y += b.y; acc1.z += b.z; acc1.w += b.w;
        }
    }

    float r = 1.0f / fmaxf((float)deg, 1.0f);
    float4* out = (float4*)(mean + (size_t)gw * D);
    acc0.x = u2f(f2tf(acc0.x * r)); acc0.y = u2f(f2tf(acc0.y * r));
    acc0.z = u2f(f2tf(acc0.z * r)); acc0.w = u2f(f2tf(acc0.w * r));
    acc1.x = u2f(f2tf(acc1.x * r)); acc1.y = u2f(f2tf(acc1.y * r));
    acc1.z = u2f(f2tf(acc1.z * r)); acc1.w = u2f(f2tf(acc1.w * r));
    out[lane]      = acc0;
    out[lane + 32] = acc1;
}

// ---------------- fused SAGE GEMM (TF32, R10 exact) ----------------------------
// C[m,:] = mean[m] @ Wl + h_dst[m] @ Wr + b   (optional ReLU, optional tf32-round)
// Block 128x128, 8 warps (4x2), warp tile 32x64, BK=16, double-buffered cp.async.

#define AS_STRIDE 20
#define BS_STRIDE 136
#define ABUF (128 * AS_STRIDE)
#define BBUF (16 * BS_STRIDE)

__device__ __forceinline__ uint32_t smem_u32(const void* p) {
    uint32_t a;
    asm("{ .reg .u64 t; cvta.to.shared.u64 t, %1; cvt.u32.u64 %0, t; }"
        : "=r"(a) : "l"(p));
    return a;
}
__device__ __forceinline__ void cp_async16(uint32_t dst, const void* src, int srcsize) {
    asm volatile("cp.async.ca.shared.global [%0], [%1], 16, %2;"
                 :: "r"(dst), "l"(src), "r"(srcsize) : "memory");
}

__device__ __forceinline__ void mma_tf32(float c[4], const unsigned a[4],
                                         unsigned b0, unsigned b1) {
    asm volatile(
        "mma.sync.aligned.m16n8k8.row.col.f32.tf32.tf32.f32 "
        "{%0,%1,%2,%3}, {%4,%5,%6,%7}, {%8,%9}, {%0,%1,%2,%3};"
        : "+f"(c[0]), "+f"(c[1]), "+f"(c[2]), "+f"(c[3])
        : "r"(a[0]), "r"(a[1]), "r"(a[2]), "r"(a[3]), "r"(b0), "r"(b1));
}

__global__ void __launch_bounds__(256, 2)
sage_gemm_tc(const float* __restrict__ A1,   // [M, 256] rounded mean
             const float* __restrict__ A2,   // [M, 256] h_dst (rounded or raw)
             const float* __restrict__ Wl,   // rounded
             const float* __restrict__ Wr,   // rounded
             const float* __restrict__ bias, // raw fp32
             float* __restrict__ C,
             int M, int do_relu, int round_out) {
    __shared__ float As[2 * ABUF];
    __shared__ float Bs[2 * BBUF];

    const int tid  = threadIdx.x;
    const int lane = tid & 31;
    const int warp = tid >> 5;
    const int wm   = warp >> 1;
    const int wn   = warp & 1;
    const int row0 = blockIdx.y * 128;
    const int col0 = blockIdx.x * 128;

    const int arow_l = tid >> 1;
    const int akslot = (tid & 1) * 8;
    const int brow_l = tid >> 4;
    const int bcol_l = (tid & 15) * 8;

    const int garow = row0 + arow_l;
    const int apred = (garow < M) ? 16 : 0;
    const size_t garow_c = (garow < M) ? (size_t)garow : 0;

    const uint32_t as_b = smem_u32(As) + (arow_l * AS_STRIDE + akslot) * 4;
    const uint32_t bs_b = smem_u32(Bs) + (brow_l * BS_STRIDE + bcol_l) * 4;

    float acc[2][8][4];
#pragma unroll
    for (int mi = 0; mi < 2; mi++)
#pragma unroll
        for (int ni = 0; ni < 8; ni++)
#pragma unroll
            for (int j = 0; j < 4; j++) acc[mi][ni][j] = 0.0f;

    const int lr = lane >> 2;
    const int lc = lane & 3;

    // it in [0,32): phase = it>>4, k0 = (it&15)*16
#define STAGE_ASYNC(it)                                                        \
    {                                                                          \
        const int phase_ = (it) >> 4;                                          \
        const int k0_    = ((it) & 15) << 4;                                   \
        const float* Ap = phase_ ? A2 : A1;                                    \
        const float* Bp = phase_ ? Wr : Wl;                                    \
        const int buf_ = (it) & 1;                                             \
        const float* ag = Ap + garow_c * D + k0_ + akslot;                     \
        cp_async16(as_b + buf_ * (ABUF * 4),      ag,     apred);              \
        cp_async16(as_b + buf_ * (ABUF * 4) + 16, ag + 4, apred);              \
        const float* bg = Bp + (size_t)(k0_ + brow_l) * D + col0 + bcol_l;     \
        cp_async16(bs_b + buf_ * (BBUF * 4),      bg,     16);                 \
        cp_async16(bs_b + buf_ * (BBUF * 4) + 16, bg + 4, 16);                 \
        asm volatile("cp.async.commit_group;" ::: "memory");                   \
    }

#define COMPUTE(buf)                                                           \
    {                                                                          \
        const float* as_ = &As[(buf) * ABUF];                                  \
        const float* bs_ = &Bs[(buf) * BBUF];                                  \
        _Pragma("unroll") for (int ks = 0; ks < 2; ks++) {                     \
            const int k8 = ks * 8;                                             \
            unsigned a[2][4];                                                  \
            _Pragma("unroll") for (int mi = 0; mi < 2; mi++) {                 \
                const int rb = wm * 32 + mi * 16 + lr;                         \
                a[mi][0] = fu(as_[rb * AS_STRIDE + k8 + lc]);                  \
                a[mi][1] = fu(as_[(rb + 8) * AS_STRIDE + k8 + lc]);            \
                a[mi][2] = fu(as_[rb * AS_STRIDE + k8 + lc + 4]);              \
                a[mi][3] = fu(as_[(rb + 8) * AS_STRIDE + k8 + lc + 4]);        \
            }                                                                  \
            _Pragma("unroll") for (int ni = 0; ni < 8; ni++) {                 \
                const int nb = wn * 64 + ni * 8 + lr;                          \
                unsigned b0 = fu(bs_[(k8 + lc) * BS_STRIDE + nb]);             \
                unsigned b1 = fu(bs_[(k8 + lc + 4) * BS_STRIDE + nb]);         \
                mma_tf32(acc[0][ni], a[0], b0, b1);                            \
                mma_tf32(acc[1][ni], a[1], b0, b1);                            \
            }                                                                  \
        }                                                                      \
    }

    STAGE_ASYNC(0);

    for (int it = 0; it < 32; it++) {
        asm volatile("cp.async.wait_group 0;" ::: "memory");
        __syncthreads();
        if (it < 31) STAGE_ASYNC(it + 1);
        COMPUTE(it & 1);
    }

    // epilogue
#pragma unroll
    for (int mi = 0; mi < 2; mi++) {
        const int r = row0 + wm * 32 + mi * 16 + lr;
#pragma unroll
        for (int ni = 0; ni < 8; ni++) {
            const int cidx = col0 + wn * 64 + ni * 8 + lc * 2;
            const float bb0 = bias[cidx];
            const float bb1 = bias[cidx + 1];
            float v0 = acc[mi][ni][0] + bb0;
            float v1 = acc[mi][ni][1] + bb1;
            float v2 = acc[mi][ni][2] + bb0;
            float v3 = acc[mi][ni][3] + bb1;
            if (do_relu) {
                v0 = fmaxf(v0, 0.f); v1 = fmaxf(v1, 0.f);
                v2 = fmaxf(v2, 0.f); v3 = fmaxf(v3, 0.f);
            }
            if (round_out) {
                v0 = u2f(f2tf(v0)); v1 = u2f(f2tf(v1));
                v2 = u2f(f2tf(v2)); v3 = u2f(f2tf(v3));
            }
            if (r < M) {
                C[(size_t)r * D + cidx]     = v0;
                C[(size_t)r * D + cidx + 1] = v1;
            }
            if (r + 8 < M) {
                C[(size_t)(r + 8) * D + cidx]     = v2;
                C[(size_t)(r + 8) * D + cidx + 1] = v3;
            }
        }
    }
}

// ---------------- launch -----------------------------------------------------
extern "C" void kernel_launch(void* const* d_in, const int* in_sizes, int n_in,
                              void* d_out, int out_size) {
    const float* x   = (const float*)d_in[0];
    const void*  e0  = d_in[1];
    const void*  e1  = d_in[2];
    const void*  e2  = d_in[3];
    const float* Wl0 = (const float*)d_in[4];
    const float* b0  = (const float*)d_in[5];
    const float* Wr0 = (const float*)d_in[6];
    const float* Wl1 = (const float*)d_in[7];
    const float* b1  = (const float*)d_in[8];
    const float* Wr1 = (const float*)d_in[9];
    const float* Wl2 = (const float*)d_in[10];
    const float* b2  = (const float*)d_in[11];
    const float* Wr2 = (const float*)d_in[12];
    float* out = (float*)d_out;

    float *mean, *h1, *h2, *wt;
    int *bcnt, *bins0, *bins1, *bins2;
    cudaGetSymbolAddress((void**)&mean,  g_mean);
    cudaGetSymbolAddress((void**)&h1,    g_h1);
    cudaGetSymbolAddress((void**)&h2,    g_h2);
    cudaGetSymbolAddress((void**)&wt,    g_wt);
    cudaGetSymbolAddress((void**)&bcnt,  g_bcnt);
    cudaGetSymbolAddress((void**)&bins0, g_bins0);
    cudaGetSymbolAddress((void**)&bins1, g_bins1);
    cudaGetSymbolAddress((void**)&bins2, g_bins2);

    int* bcnt0 = bcnt;
    int* bcnt1 = bcnt + N1;
    int* bcnt2 = bcnt + N1 + N2;

    const float* wl0t = wt + 0 * D * D;
    const float* wr0t = wt + 1 * D * D;
    const float* wl1t = wt + 2 * D * D;
    const float* wr1t = wt + 3 * D * D;
    const float* wl2t = wt + 4 * D * D;
    const float* wr2t = wt + 5 * D * D;

    // prep: zero all counters, detect dtype, round all weights (1 launch)
    prep_kernel<<<(PREP_THREADS + 255) / 256, 256>>>(
        (const int*)e0, Wl0, Wr0, Wl1, Wr1, Wl2, Wr2, bcnt, (float4*)wt);

    // bin all 3 layers (1 launch)
    bin_all_kernel<<<(E0 + E1 + E2 + 255) / 256, 256>>>(e0, e1, e2, bcnt);

    // ---- layer 0: x[N0] -> h1[N1]
    gather_kernel<<<(N1 * 32 + 255) / 256, 256>>>(x, bcnt0, bins0, e0, E0, mean, N1);
    sage_gemm_tc<<<dim3(2, (N1 + 127) / 128), 256>>>(
        mean, x, wl0t, wr0t, b0, h1, N1, 1, 1);

    // ---- layer 1: h1[N1] -> h2[N2]
    gather_kernel<<<(N2 * 32 + 255) / 256, 256>>>(h1, bcnt1, bins1, e1, E1, mean, N2);
    sage_gemm_tc<<<dim3(2, (N2 + 127) / 128), 256>>>(
        mean, h1, wl1t, wr1t, b1, h2, N2, 1, 1);

    // ---- layer 2: h2[N2] -> out[N3] (no ReLU, exact store)
    gather_kernel<<<(N3 * 32 + 255) / 256, 256>>>(h2, bcnt2, bins2, e2, E2, mean, N3);
    sage_gemm_tc<<<dim3(2, (N3 + 127) / 128), 256>>>(
        mean, h2, wl2t, wr2t, b2, out, N3, 0, 0);
}

// round 13
// speedup vs baseline: 1.4572x; 1.0159x over previous
#include <cuda_runtime.h>
#include <cstdint>

// Problem constants
#define N0 100000
#define N1 50000
#define N2 25000
#define N3 12500
#define E0 800000
#define E1 400000
#define E2 200000
#define D  256
#define MAXDEG 64

// ---------------- scratch (device globals; no allocation allowed) ----------
__device__ float g_mean[N1 * D];          // rounded means (A1)
__device__ float g_h1[N1 * D];            // rounded layer outputs
__device__ float g_h2[N2 * D];
__device__ float g_wt[6 * D * D];         // tf32-rounded weights
__device__ int   g_bcnt[N1 + N2 + N3];    // per-layer degree arrays
__device__ int   g_bins0[N1 * MAXDEG];    // per-layer per-dst src lists
__device__ int   g_bins1[N2 * MAXDEG];
__device__ int   g_bins2[N3 * MAXDEG];
__device__ int   g_is64;

__device__ __forceinline__ unsigned f2tf(float f) {
    unsigned u;
    asm("cvt.rna.tf32.f32 %0, %1;" : "=r"(u) : "f"(f));
    return u;
}
__device__ __forceinline__ unsigned fu(float f) { return __float_as_uint(f); }
__device__ __forceinline__ float u2f(unsigned u) { return __uint_as_float(u); }

// ---------------- prep: zero counters + detect + round weights (one kernel) ---
#define NCNT (N1 + N2 + N3)
__global__ void prep_kernel(const int* __restrict__ e0,
                            const float* __restrict__ w0, const float* __restrict__ w1,
                            const float* __restrict__ w2, const float* __restrict__ w3,
                            const float* __restrict__ w4, const float* __restrict__ w5,
                            int* __restrict__ bcnt, float4* __restrict__ wt) {
    int i = blockIdx.x * blockDim.x + threadIdx.x;
    if (i == 0) {
        int is64 = 1;
        for (int k = 1; k < 64; k += 2)
            if (e0[k] != 0) is64 = 0;
        g_is64 = is64;
    }
    if (i < NCNT) bcnt[i] = 0;
    int j = i - NCNT;
    if (j >= 0 && j < 6 * (D * D / 4)) {
        int seg = j / (D * D / 4);
        int off = j - seg * (D * D / 4);
        const float4* src;
        switch (seg) {
            case 0: src = (const float4*)w0; break;
            case 1: src = (const float4*)w1; break;
            case 2: src = (const float4*)w2; break;
            case 3: src = (const float4*)w3; break;
            case 4: src = (const float4*)w4; break;
            default: src = (const float4*)w5; break;
        }
        float4 v = src[off];
        v.x = u2f(f2tf(v.x)); v.y = u2f(f2tf(v.y));
        v.z = u2f(f2tf(v.z)); v.w = u2f(f2tf(v.w));
        wt[j] = v;
    }
}
#define PREP_THREADS (NCNT + 6 * (D * D / 4))

// ---------------- merged edge binning (all 3 layers, one launch) ---------------
__global__ void bin_all_kernel(const void* __restrict__ e0raw,
                               const void* __restrict__ e1raw,
                               const void* __restrict__ e2raw,
                               int* __restrict__ bcnt) {
    int i = blockIdx.x * blockDim.x + threadIdx.x;
    const void* eraw;
    int E, li;
    int* bc;
    int* bins;
    if (i < E0) {
        eraw = e0raw; E = E0; li = i; bc = bcnt; bins = g_bins0;
    } else if (i < E0 + E1) {
        eraw = e1raw; E = E1; li = i - E0; bc = bcnt + N1; bins = g_bins1;
    } else if (i < E0 + E1 + E2) {
        eraw = e2raw; E = E2; li = i - E0 - E1; bc = bcnt + N1 + N2; bins = g_bins2;
    } else {
        return;
    }
    int s, d;
    if (g_is64) {
        const long long* e = (const long long*)eraw;
        s = (int)e[li];
        d = (int)e[(long long)E + li];
    } else {
        const int* e = (const int*)eraw;
        s = e[li];
        d = e[E + li];
    }
    int slot = atomicAdd(&bc[d], 1);
    if (slot < MAXDEG) bins[d * MAXDEG + slot] = s;
    // slot >= MAXDEG: gather rescans the edge list for this dst (never in practice)
}

// ---------------- gather-mean: one warp per dst row (R10 exact) ----------------
__global__ void __launch_bounds__(256)
gather_kernel(const float* __restrict__ h,
              const int* __restrict__ bcnt,
              const int* __restrict__ bins,
              const void* __restrict__ eraw, int E,
              float* __restrict__ mean, int M) {
    int gw   = (blockIdx.x * blockDim.x + threadIdx.x) >> 5;
    int lane = threadIdx.x & 31;
    if (gw >= M) return;

    int deg = bcnt[gw];

    float4 acc0 = make_float4(0.f, 0.f, 0.f, 0.f);
    float4 acc1 = make_float4(0.f, 0.f, 0.f, 0.f);

    if (deg <= MAXDEG) {
        int src0 = 0, src1 = 0;
        if (lane < deg)      src0 = bins[gw * MAXDEG + lane];
        if (lane + 32 < deg) src1 = bins[gw * MAXDEG + lane + 32];
        for (int i = 0; i < deg; i++) {
            int s = (i < 32) ? __shfl_sync(0xffffffffu, src0, i)
                             : __shfl_sync(0xffffffffu, src1, i - 32);
            const float4* row = (const float4*)(h + (size_t)s * D);
            float4 a = row[lane];
            float4 b = row[lane + 32];
            acc0.x += a.x; acc0.y += a.y; acc0.z += a.z; acc0.w += a.w;
            acc1.x += b.x; acc1.y += b.y; acc1.z += b.z; acc1.w += b.w;
        }
    } else {
        int is64 = g_is64;
        for (int i = 0; i < E; i++) {
            int s, d;
            if (is64) {
                const long long* e = (const long long*)eraw;
                d = (int)e[(long long)E + i];
                if (d != gw) continue;
                s = (int)e[i];
            } else {
                const int* e = (const int*)eraw;
                d = e[E + i];
                if (d != gw) continue;
                s = e[i];
            }
            const float4* row = (const float4*)(h + (size_t)s * D);
            float4 a = row[lane];
            float4 b = row[lane + 32];
            acc0.x += a.x; acc0.y += a.y; acc0.z += a.z; acc0.w += a.w;
            acc1.x += b.x; acc1.y += b.y; acc1.z += b.z; acc1.w += b.w;
        }
    }

    float r = 1.0f / fmaxf((float)deg, 1.0f);
    float4* out = (float4*)(mean + (size_t)gw * D);
    acc0.x = u2f(f2tf(acc0.x * r)); acc0.y = u2f(f2tf(acc0.y * r));
    acc0.z = u2f(f2tf(acc0.z * r)); acc0.w = u2f(f2tf(acc0.w * r));
    acc1.x = u2f(f2tf(acc1.x * r)); acc1.y = u2f(f2tf(acc1.y * r));
    acc1.z = u2f(f2tf(acc1.z * r)); acc1.w = u2f(f2tf(acc1.w * r));
    out[lane]      = acc0;
    out[lane + 32] = acc1;
}

// ---------------- fused SAGE GEMM (TF32, R12 layout + 3-stage cp.async) --------
// C[m,:] = mean[m] @ Wl + h_dst[m] @ Wr + b   (optional ReLU, optional tf32-round)
// Block 128x128, 8 warps (4x2), warp tile 32x64, BK=16.
// Only change vs R12: 3-deep cp.async ring (wait_group 1, prefetch distance 2)
// to cover L2/DRAM latency at chunk boundaries. Dynamic smem 56.8 KB, 2 CTA/SM.

#define AS_STRIDE 20
#define BS_STRIDE 136
#define ABUF (128 * AS_STRIDE)
#define BBUF (16 * BS_STRIDE)
#define NSTAGE 3
#define GEMM_SMEM (NSTAGE * (ABUF + BBUF) * (int)sizeof(float))

__device__ __forceinline__ uint32_t smem_u32(const void* p) {
    uint32_t a;
    asm("{ .reg .u64 t; cvta.to.shared.u64 t, %1; cvt.u32.u64 %0, t; }"
        : "=r"(a) : "l"(p));
    return a;
}
__device__ __forceinline__ void cp_async16(uint32_t dst, const void* src, int srcsize) {
    asm volatile("cp.async.ca.shared.global [%0], [%1], 16, %2;"
                 :: "r"(dst), "l"(src), "r"(srcsize) : "memory");
}

__device__ __forceinline__ void mma_tf32(float c[4], const unsigned a[4],
                                         unsigned b0, unsigned b1) {
    asm volatile(
        "mma.sync.aligned.m16n8k8.row.col.f32.tf32.tf32.f32 "
        "{%0,%1,%2,%3}, {%4,%5,%6,%7}, {%8,%9}, {%0,%1,%2,%3};"
        : "+f"(c[0]), "+f"(c[1]), "+f"(c[2]), "+f"(c[3])
        : "r"(a[0]), "r"(a[1]), "r"(a[2]), "r"(a[3]), "r"(b0), "r"(b1));
}

__global__ void __launch_bounds__(256, 2)
sage_gemm_tc(const float* __restrict__ A1,   // [M, 256] rounded mean
             const float* __restrict__ A2,   // [M, 256] h_dst (rounded or raw)
             const float* __restrict__ Wl,   // rounded
             const float* __restrict__ Wr,   // rounded
             const float* __restrict__ bias, // raw fp32
             float* __restrict__ C,
             int M, int do_relu, int round_out) {
    extern __shared__ float dynsm[];
    float* AsP = dynsm;                 // NSTAGE * ABUF
    float* BsP = dynsm + NSTAGE * ABUF; // NSTAGE * BBUF

    const int tid  = threadIdx.x;
    const int lane = tid & 31;
    const int warp = tid >> 5;
    const int wm   = warp >> 1;
    const int wn   = warp & 1;
    const int row0 = blockIdx.y * 128;
    const int col0 = blockIdx.x * 128;

    const int arow_l = tid >> 1;
    const int akslot = (tid & 1) * 8;
    const int brow_l = tid >> 4;
    const int bcol_l = (tid & 15) * 8;

    const int garow = row0 + arow_l;
    const int apred = (garow < M) ? 16 : 0;
    const size_t garow_c = (garow < M) ? (size_t)garow : 0;

    const uint32_t as_b = smem_u32(AsP) + (arow_l * AS_STRIDE + akslot) * 4;
    const uint32_t bs_b = smem_u32(BsP) + (brow_l * BS_STRIDE + bcol_l) * 4;

    float acc[2][8][4];
#pragma unroll
    for (int mi = 0; mi < 2; mi++)
#pragma unroll
        for (int ni = 0; ni < 8; ni++)
#pragma unroll
            for (int j = 0; j < 4; j++) acc[mi][ni][j] = 0.0f;

    const int lr = lane >> 2;
    const int lc = lane & 3;

    // it in [0,32): phase = it>>4, k0 = (it&15)*16; buf passed explicitly
#define STAGE_ASYNC(it, buf)                                                   \
    {                                                                          \
        const int phase_ = (it) >> 4;                                          \
        const int k0_    = ((it) & 15) << 4;                                   \
        const float* Ap = phase_ ? A2 : A1;                                    \
        const float* Bp = phase_ ? Wr : Wl;                                    \
        const float* ag = Ap + garow_c * D + k0_ + akslot;                     \
        cp_async16(as_b + (buf) * (ABUF * 4),      ag,     apred);             \
        cp_async16(as_b + (buf) * (ABUF * 4) + 16, ag + 4, apred);             \
        const float* bg = Bp + (size_t)(k0_ + brow_l) * D + col0 + bcol_l;     \
        cp_async16(bs_b + (buf) * (BBUF * 4),      bg,     16);                \
        cp_async16(bs_b + (buf) * (BBUF * 4) + 16, bg + 4, 16);                \
        asm volatile("cp.async.commit_group;" ::: "memory");                   \
    }

#define COMPUTE(buf)                                                           \
    {                                                                          \
        const float* as_ = &AsP[(buf) * ABUF];                                 \
        const float* bs_ = &BsP[(buf) * BBUF];                                 \
        _Pragma("unroll") for (int ks = 0; ks < 2; ks++) {                     \
            const int k8 = ks * 8;                                             \
            unsigned a[2][4];                                                  \
            _Pragma("unroll") for (int mi = 0; mi < 2; mi++) {                 \
                const int rb = wm * 32 + mi * 16 + lr;                         \
                a[mi][0] = fu(as_[rb * AS_STRIDE + k8 + lc]);                  \
                a[mi][1] = fu(as_[(rb + 8) * AS_STRIDE + k8 + lc]);            \
                a[mi][2] = fu(as_[rb * AS_STRIDE + k8 + lc + 4]);              \
                a[mi][3] = fu(as_[(rb + 8) * AS_STRIDE + k8 + lc + 4]);        \
            }                                                                  \
            _Pragma("unroll") for (int ni = 0; ni < 8; ni++) {                 \
                const int nb = wn * 64 + ni * 8 + lr;                          \
                unsigned b0 = fu(bs_[(k8 + lc) * BS_STRIDE + nb]);             \
                unsigned b1 = fu(bs_[(k8 + lc + 4) * BS_STRIDE + nb]);         \
                mma_tf32(acc[0][ni], a[0], b0, b1);                            \
                mma_tf32(acc[1][ni], a[1], b0, b1);                            \
            }                                                                  \
        }                                                                      \
    }

    STAGE_ASYNC(0, 0);
    STAGE_ASYNC(1, 1);

    int cb = 0;   // compute buffer = it % 3
    int sb = 2;   // stage buffer   = (it + 2) % 3
    for (int it = 0; it < 32; it++) {
        if (it < 31) {
            asm volatile("cp.async.wait_group 1;" ::: "memory");
        } else {
            asm volatile("cp.async.wait_group 0;" ::: "memory");
        }
        __syncthreads();
        if (it + 2 < 32) STAGE_ASYNC(it + 2, sb);
        COMPUTE(cb);
        cb = (cb == 2) ? 0 : cb + 1;
        sb = (sb == 2) ? 0 : sb + 1;
    }

    // epilogue
#pragma unroll
    for (int mi = 0; mi < 2; mi++) {
        const int r = row0 + wm * 32 + mi * 16 + lr;
#pragma unroll
        for (int ni = 0; ni < 8; ni++) {
            const int cidx = col0 + wn * 64 + ni * 8 + lc * 2;
            const float bb0 = bias[cidx];
            const float bb1 = bias[cidx + 1];
            float v0 = acc[mi][ni][0] + bb0;
            float v1 = acc[mi][ni][1] + bb1;
            float v2 = acc[mi][ni][2] + bb0;
            float v3 = acc[mi][ni][3] + bb1;
            if (do_relu) {
                v0 = fmaxf(v0, 0.f); v1 = fmaxf(v1, 0.f);
                v2 = fmaxf(v2, 0.f); v3 = fmaxf(v3, 0.f);
            }
            if (round_out) {
                v0 = u2f(f2tf(v0)); v1 = u2f(f2tf(v1));
                v2 = u2f(f2tf(v2)); v3 = u2f(f2tf(v3));
            }
            if (r < M) {
                C[(size_t)r * D + cidx]     = v0;
                C[(size_t)r * D + cidx + 1] = v1;
            }
            if (r + 8 < M) {
                C[(size_t)(r + 8) * D + cidx]     = v2;
                C[(size_t)(r + 8) * D + cidx + 1] = v3;
            }
        }
    }
}

// ---------------- launch -----------------------------------------------------
extern "C" void kernel_launch(void* const* d_in, const int* in_sizes, int n_in,
                              void* d_out, int out_size) {
    const float* x   = (const float*)d_in[0];
    const void*  e0  = d_in[1];
    const void*  e1  = d_in[2];
    const void*  e2  = d_in[3];
    const float* Wl0 = (const float*)d_in[4];
    const float* b0  = (const float*)d_in[5];
    const float* Wr0 = (const float*)d_in[6];
    const float* Wl1 = (const float*)d_in[7];
    const float* b1  = (const float*)d_in[8];
    const float* Wr1 = (const float*)d_in[9];
    const float* Wl2 = (const float*)d_in[10];
    const float* b2  = (const float*)d_in[11];
    const float* Wr2 = (const float*)d_in[12];
    float* out = (float*)d_out;

    float *mean, *h1, *h2, *wt;
    int *bcnt, *bins0, *bins1, *bins2;
    cudaGetSymbolAddress((void**)&mean,  g_mean);
    cudaGetSymbolAddress((void**)&h1,    g_h1);
    cudaGetSymbolAddress((void**)&h2,    g_h2);
    cudaGetSymbolAddress((void**)&wt,    g_wt);
    cudaGetSymbolAddress((void**)&bcnt,  g_bcnt);
    cudaGetSymbolAddress((void**)&bins0, g_bins0);
    cudaGetSymbolAddress((void**)&bins1, g_bins1);
    cudaGetSymbolAddress((void**)&bins2, g_bins2);

    int* bcnt0 = bcnt;
    int* bcnt1 = bcnt + N1;
    int* bcnt2 = bcnt + N1 + N2;

    const float* wl0t = wt + 0 * D * D;
    const float* wr0t = wt + 1 * D * D;
    const float* wl1t = wt + 2 * D * D;
    const float* wr1t = wt + 3 * D * D;
    const float* wl2t = wt + 4 * D * D;
    const float* wr2t = wt + 5 * D * D;

    cudaFuncSetAttribute(sage_gemm_tc,
                         cudaFuncAttributeMaxDynamicSharedMemorySize, GEMM_SMEM);

    // prep: zero all counters, detect dtype, round all weights (1 launch)
    prep_kernel<<<(PREP_THREADS + 255) / 256, 256>>>(
        (const int*)e0, Wl0, Wr0, Wl1, Wr1, Wl2, Wr2, bcnt, (float4*)wt);

    // bin all 3 layers (1 launch)
    bin_all_kernel<<<(E0 + E1 + E2 + 255) / 256, 256>>>(e0, e1, e2, bcnt);

    // ---- layer 0: x[N0] -> h1[N1]
    gather_kernel<<<(N1 * 32 + 255) / 256, 256>>>(x, bcnt0, bins0, e0, E0, mean, N1);
    sage_gemm_tc<<<dim3(2, (N1 + 127) / 128), 256, GEMM_SMEM>>>(
        mean, x, wl0t, wr0t, b0, h1, N1, 1, 1);

    // ---- layer 1: h1[N1] -> h2[N2]
    gather_kernel<<<(N2 * 32 + 255) / 256, 256>>>(h1, bcnt1, bins1, e1, E1, mean, N2);
    sage_gemm_tc<<<dim3(2, (N2 + 127) / 128), 256, GEMM_SMEM>>>(
        mean, h1, wl1t, wr1t, b1, h2, N2, 1, 1);

    // ---- layer 2: h2[N2] -> out[N3] (no ReLU, exact store)
    gather_kernel<<<(N3 * 32 + 255) / 256, 256>>>(h2, bcnt2, bins2, e2, E2, mean, N3);
    sage_gemm_tc<<<dim3(2, (N3 + 127) / 128), 256, GEMM_SMEM>>>(
        mean, h2, wl2t, wr2t, b2, out, N3, 0, 0);
}